// round 11
// baseline (speedup 1.0000x reference)
#include <cuda_runtime.h>
#include <math_constants.h>

#define HH 224
#define WW 224
#define HWP (HH * WW)      // 50176
#define BB 64
#define RBLK 16            // reduce-role blocks per batch
#define NRED (BB * RBLK)   // 1024
#define FBLK 49            // fill-role blocks per batch
#define NFILL (BB * FBLK)  // 3136
#define NQ (HWP / 4)       // 12544 float4 tiles per image

// Per-(batch, block) partial min/max. Plain stores (no init needed).
__device__ float g_pmax[BB][RBLK];
__device__ float g_pmin[BB][RBLK];
// Tickets/flags. Zero at module load; winners reset -> replay-safe.
__device__ int g_cnt[BB];    // reduce completion ticket
__device__ int g_done[BB];   // fill consumption ticket (resets g_flag)
__device__ int g_flag[BB];   // scalars-ready flag
// Per-batch scalars: [pd, fr, hp0f, hp1f] [gx, gy, rn2, pad]
__device__ float4 g_scal[BB][2];

// ---------------------------------------------------------------------------
// One launch, two roles, minimal coupling:
//  * reduce role (bids 0..1023, batch-major): per-batch min/max partials;
//    last ticket publishes g_scal[b] and releases g_flag[b]. Never waits.
//  * fill role (bids 1024.., batch-major): conservative cone gate from raw
//    gaze/hp. Out-of-cone threads (~92%) stream exact zeros -- no input
//    loads, no flag. Only in-cone threads wait for g_flag[b]; reduce blocks
//    all sit in wave 1 (grid order), so waves 2+ find the flag already set.
// ---------------------------------------------------------------------------
__global__ void __launch_bounds__(256)
fused_kernel(const float* __restrict__ depth, const float* __restrict__ obj,
             const float* __restrict__ gaze, const long long* __restrict__ hp,
             float* __restrict__ out) {
    const int bid = blockIdx.x;

    if (bid < NRED) {
        // ------------- reduce role -------------
        const int b    = bid / RBLK;
        const int rblk = bid % RBLK;

        // Thread 0 prefetches scalar inputs at entry; the dependent chain
        // (hp -> head pixel -> product) overlaps the reduction loop.
        int hp0 = 0, hp1 = 0;
        float gx = 0.f, gy = 0.f, gz = 0.f, hd = 0.f;
        if (threadIdx.x == 0) {
            hp0 = (int)hp[2 * b];
            hp1 = (int)hp[2 * b + 1];
            gx = gaze[3 * b]; gy = gaze[3 * b + 1]; gz = gaze[3 * b + 2];
            size_t hidx = (size_t)b * HWP + (size_t)hp0 * WW + hp1;
            hd = depth[hidx] * obj[hidx];
        }

        const float4* dp = reinterpret_cast<const float4*>(depth + (size_t)b * HWP);
        const float4* op = reinterpret_cast<const float4*>(obj + (size_t)b * HWP);
        float mx = -CUDART_INF_F, mn = CUDART_INF_F;
        for (int i = rblk * 256 + threadIdx.x; i < NQ; i += RBLK * 256) {
            float4 d = dp[i];
            float4 o = op[i];
            float p0 = d.x * o.x, p1 = d.y * o.y, p2 = d.z * o.z, p3 = d.w * o.w;
            mx = fmaxf(mx, fmaxf(fmaxf(p0, p1), fmaxf(p2, p3)));
            mn = fminf(mn, fminf(fminf(p0, p1), fminf(p2, p3)));
        }
#pragma unroll
        for (int off = 16; off; off >>= 1) {
            mx = fmaxf(mx, __shfl_xor_sync(0xffffffffu, mx, off));
            mn = fminf(mn, __shfl_xor_sync(0xffffffffu, mn, off));
        }
        __shared__ float smx[8], smn[8];
        int w = threadIdx.x >> 5, l = threadIdx.x & 31;
        if (l == 0) { smx[w] = mx; smn[w] = mn; }
        __syncthreads();
        if (threadIdx.x == 0) {
#pragma unroll
            for (int i = 1; i < 8; i++) {
                mx = fmaxf(mx, smx[i]);
                mn = fminf(mn, smn[i]);
            }
            g_pmax[b][rblk] = mx;
            g_pmin[b][rblk] = mn;
            __threadfence();
            int ticket = atomicAdd(&g_cnt[b], 1);
            if (ticket == RBLK - 1) {
                g_cnt[b] = 0;        // reset for next graph replay
                float fmx = -CUDART_INF_F, fmn = CUDART_INF_F;
#pragma unroll
                for (int i = 0; i < RBLK; i++) {
                    fmx = fmaxf(fmx, g_pmax[b][i]);
                    fmn = fminf(fmn, g_pmin[b][i]);
                }
                g_scal[b][0] = make_float4(hd + gz * 224.0f,      // pd
                                           (fmx - fmn) / 24.0f,   // fr
                                           (float)hp0, (float)hp1);
                g_scal[b][1] = make_float4(gx, gy, gx * gx + gy * gy, 0.f);
                __threadfence();
                atomicExch(&g_flag[b], 1);   // release
            }
        }
        return;
    }

    // ------------- fill role -------------
    const int mb = bid - NRED;
    const int b  = mb / FBLK;
    const int lb = mb % FBLK;

    const int idx = lb * 256 + threadIdx.x;  // float4 tile in image
    const int pix = idx * 4;
    const int h   = pix / WW;
    const int w0  = pix % WW;

    // Warp-uniform raw scalar loads (broadcast sectors, L2-hot). These do
    // NOT depend on the reduction.
    const float gx = gaze[3 * b];
    const float gy = gaze[3 * b + 1];
    const float hp0f = (float)(int)hp[2 * b];
    const float hp1f = (float)(int)hp[2 * b + 1];
    const float rn2 = gx * gx + gy * gy;

    const float a1   = (float)h - hp1f;
    const float a1gy = a1 * gy;
    const float a1sq = a1 * a1;
    const float a0b  = (float)w0 - hp0f;

    // Conservative FMA-only cone gate (dot>0 && dot^2>c*tt <=> dot*|dot|>c*tt).
    // 0.93 < cos^2(pi/12)=0.93301: strictly looser than the exact test, so fp
    // noise only sends extra threads to the exact path, never skips a hit.
    bool any = false;
#pragma unroll
    for (int j = 0; j < 4; j++) {
        float a0  = a0b + (float)j;          // exact (small ints in fp32)
        float dot = fmaf(a0, gx, a1gy);
        float tt  = fmaf(a0, a0, a1sq) * rn2;
        any = any || (dot * fabsf(dot) > 0.93f * tt);
    }

    float* op0 = out + (size_t)b * 3 * HWP + pix;

    if (!any) {
        // mask == 0 for all 4 pixels: all channels exactly 0 regardless of d
        // (finite * 0 == 0 in the reference too). No data loads, no waiting.
        const float4 z = make_float4(0.f, 0.f, 0.f, 0.f);
        *reinterpret_cast<float4*>(op0)           = z;
        *reinterpret_cast<float4*>(op0 + HWP)     = z;
        *reinterpret_cast<float4*>(op0 + 2 * HWP) = z;
    } else {
        // In-cone (~8% of threads). Prefetch pixel data (independent of the
        // scalars) so its latency hides behind the flag check.
        const float4 d4 = *reinterpret_cast<const float4*>(depth + (size_t)b * HWP + pix);
        const float4 o4 = *reinterpret_cast<const float4*>(obj   + (size_t)b * HWP + pix);

        // Wait for this batch's scalars. Reduce blocks (the producers) never
        // wait on anything -> they always retire and set the flag -> no
        // deadlock. All reduce blocks are in wave 1, so this almost always
        // falls straight through.
        volatile int* f = &g_flag[b];
        while (*f == 0) { __nanosleep(64); }
        __threadfence();                     // acquire

        const float4 s0 = g_scal[b][0];
        const float4 s1 = g_scal[b][1];
        const float pd = s0.x, fr = s0.y;
        const float cf1 = fr, cf2 = 2.f * fr, cf3 = 3.f * fr;
        const float angscale = 12.0f / CUDART_PI_F;

        float dv[4] = {d4.x * o4.x, d4.y * o4.y, d4.z * o4.z, d4.w * o4.w};

        float o0[4], o1[4], o2[4];
#pragma unroll
        for (int j = 0; j < 4; j++) {
            float a0  = a0b + (float)j;
            float dot = fmaf(a0, gx, a1gy);
            float tt  = fmaf(a0, a0, a1sq) * rn2;
            float r   = dot * rsqrtf(tt);
            // Branch-free exact mask: out-of-cone -> negative -> 0; tt==0 or
            // r>1 -> NaN -> fmaxf scrubs to 0 (== nan_to_num(maximum(...))).
            float m = fmaxf(fmaf(-angscale, acosf(r), 1.0f), 0.0f);
            float d = dv[j];
            float e = fabsf(d - pd);
            float v = d * m;
            o0[j] = (e <= cf1) ? v : 0.f;
            o1[j] = (e <= cf2) ? v : 0.f;
            o2[j] = (e <= cf3) ? v : 0.f;
        }

        *reinterpret_cast<float4*>(op0)           = make_float4(o0[0], o0[1], o0[2], o0[3]);
        *reinterpret_cast<float4*>(op0 + HWP)     = make_float4(o1[0], o1[1], o1[2], o1[3]);
        *reinterpret_cast<float4*>(op0 + 2 * HWP) = make_float4(o2[0], o2[1], o2[2], o2[3]);
    }

    // Replay reset: 49th fill block of this batch clears the flag. Every
    // thread's flag read precedes its block's ticket (barrier below), and
    // the winner is the last of all 49 -> no read sees a cleared flag.
    __syncthreads();
    if (threadIdx.x == 0) {
        int t = atomicAdd(&g_done[b], 1);
        if (t == FBLK - 1) { g_done[b] = 0; g_flag[b] = 0; }
    }
}

extern "C" void kernel_launch(void* const* d_in, const int* in_sizes, int n_in,
                              void* d_out, int out_size) {
    const float* depth = (const float*)d_in[0];
    const float* obj   = (const float*)d_in[1];
    const float* gaze  = (const float*)d_in[2];
    const long long* hp = (const long long*)d_in[3];
    float* out = (float*)d_out;

    fused_kernel<<<NRED + NFILL, 256>>>(depth, obj, gaze, hp, out);
}

// round 12
// speedup vs baseline: 1.4583x; 1.4583x over previous
#include <cuda_runtime.h>
#include <math_constants.h>

#define HH 224
#define WW 224
#define HWP (HH * WW)      // 50176
#define BB 64
#define RBLK 16            // reduce-role blocks per batch
#define NRED (BB * RBLK)   // 1024
#define FBLK 49            // fill-role blocks per batch
#define NFILL (BB * FBLK)  // 3136
#define NQ (HWP / 4)       // 12544 float4 tiles per image

// Per-(batch, block) partial min/max. Plain stores (no init needed).
__device__ float g_pmax[BB][RBLK];
__device__ float g_pmin[BB][RBLK];
// Ticket per batch. Zero at module load; winner resets -> replay-safe.
__device__ int g_cnt[BB];
// Per-batch scalars: [pd, fr, hp0f, hp1f] [gx, gy, rn2, pad]
__device__ float4 g_scal[BB][2];

// ---------------------------------------------------------------------------
// Kernel 1: reduce role + pure zero-fill role. Zero coupling between roles
// (no flags, no spinning -- R6/R11 showed any intra-kernel wait is poison).
// The 25.6MB input read (reduce) and 38.5MB zero-store stream (fill) overlap
// on the SMs; the reduction finishes well inside the fill's shadow.
// ---------------------------------------------------------------------------
__global__ void __launch_bounds__(256)
fused_kernel(const float* __restrict__ depth, const float* __restrict__ obj,
             const float* __restrict__ gaze, const long long* __restrict__ hp,
             float* __restrict__ out) {
    const int bid = blockIdx.x;

    if (bid < NRED) {
        // ------------- reduce role -------------
        const int b    = bid / RBLK;
        const int rblk = bid % RBLK;

        // Thread 0 prefetches scalar inputs at entry; the dependent chain
        // (hp -> head pixel -> product) overlaps the reduction loop.
        int hp0 = 0, hp1 = 0;
        float gx = 0.f, gy = 0.f, gz = 0.f, hd = 0.f;
        if (threadIdx.x == 0) {
            hp0 = (int)hp[2 * b];
            hp1 = (int)hp[2 * b + 1];
            gx = gaze[3 * b]; gy = gaze[3 * b + 1]; gz = gaze[3 * b + 2];
            size_t hidx = (size_t)b * HWP + (size_t)hp0 * WW + hp1;
            hd = depth[hidx] * obj[hidx];
        }

        const float4* dp = reinterpret_cast<const float4*>(depth + (size_t)b * HWP);
        const float4* op = reinterpret_cast<const float4*>(obj + (size_t)b * HWP);
        float mx = -CUDART_INF_F, mn = CUDART_INF_F;
        for (int i = rblk * 256 + threadIdx.x; i < NQ; i += RBLK * 256) {
            float4 d = dp[i];
            float4 o = op[i];
            float p0 = d.x * o.x, p1 = d.y * o.y, p2 = d.z * o.z, p3 = d.w * o.w;
            mx = fmaxf(mx, fmaxf(fmaxf(p0, p1), fmaxf(p2, p3)));
            mn = fminf(mn, fminf(fminf(p0, p1), fminf(p2, p3)));
        }
#pragma unroll
        for (int off = 16; off; off >>= 1) {
            mx = fmaxf(mx, __shfl_xor_sync(0xffffffffu, mx, off));
            mn = fminf(mn, __shfl_xor_sync(0xffffffffu, mn, off));
        }
        __shared__ float smx[8], smn[8];
        int w = threadIdx.x >> 5, l = threadIdx.x & 31;
        if (l == 0) { smx[w] = mx; smn[w] = mn; }
        __syncthreads();
        if (threadIdx.x == 0) {
#pragma unroll
            for (int i = 1; i < 8; i++) {
                mx = fmaxf(mx, smx[i]);
                mn = fminf(mn, smn[i]);
            }
            g_pmax[b][rblk] = mx;
            g_pmin[b][rblk] = mn;
            __threadfence();
            int ticket = atomicAdd(&g_cnt[b], 1);
            if (ticket == RBLK - 1) {
                g_cnt[b] = 0;        // reset for next graph replay
                float fmx = -CUDART_INF_F, fmn = CUDART_INF_F;
#pragma unroll
                for (int i = 0; i < RBLK; i++) {
                    fmx = fmaxf(fmx, g_pmax[b][i]);
                    fmn = fminf(fmn, g_pmin[b][i]);
                }
                g_scal[b][0] = make_float4(hd + gz * 224.0f,      // pd
                                           (fmx - fmn) / 24.0f,   // fr
                                           (float)hp0, (float)hp1);
                g_scal[b][1] = make_float4(gx, gy, gx * gx + gy * gy, 0.f);
            }
        }
        return;
    }

    // ------------- fill role: pure zero stream -------------
    // Everything gets zero; kernel 2 overwrites the ~5% in-cone tiles after
    // the kernel boundary (the only synchronization point).
    const int mb = bid - NRED;
    const int b  = mb / FBLK;
    const int lb = mb % FBLK;
    const int pix = (lb * 256 + threadIdx.x) * 4;

    float* op0 = out + (size_t)b * 3 * HWP + pix;
    const float4 z = make_float4(0.f, 0.f, 0.f, 0.f);
    *reinterpret_cast<float4*>(op0)           = z;
    *reinterpret_cast<float4*>(op0 + HWP)     = z;
    *reinterpret_cast<float4*>(op0 + 2 * HWP) = z;
}

// ---------------------------------------------------------------------------
// Kernel 2: full-image gate re-scan, exact work on in-cone tiles only.
// Out-of-cone threads (~92%) run ~20 instructions (no data loads, no
// stores) and retire -- cheap at full occupancy, no worklist indirection.
// In-cone inputs are L2-hot from kernel 1's reduce read.
// ---------------------------------------------------------------------------
__global__ void __launch_bounds__(256)
cone_kernel(const float* __restrict__ depth, const float* __restrict__ obj,
            float* __restrict__ out) {
    const int b  = blockIdx.x / FBLK;
    const int lb = blockIdx.x % FBLK;

    const int idx = lb * 256 + threadIdx.x;  // float4 tile in image
    const int pix = idx * 4;
    const int h   = pix / WW;
    const int w0  = pix % WW;

    // Warp-uniform scalar loads (broadcast sectors, L2-hot).
    const float4 s0 = g_scal[b][0];
    const float4 s1 = g_scal[b][1];
    const float gx = s1.x, gy = s1.y, rn2 = s1.z;

    const float a1   = (float)h - s0.w;
    const float a1gy = a1 * gy;
    const float a1sq = a1 * a1;
    const float a0b  = (float)w0 - s0.z;

    // Conservative FMA-only cone gate (dot>0 && dot^2>c*tt <=> dot*|dot|>c*tt).
    // 0.93 < cos^2(pi/12)=0.93301: strictly looser than the exact test, so fp
    // noise only sends extra threads to the exact path, never skips a hit.
    bool any = false;
#pragma unroll
    for (int j = 0; j < 4; j++) {
        float a0  = a0b + (float)j;          // exact (small ints in fp32)
        float dot = fmaf(a0, gx, a1gy);
        float tt  = fmaf(a0, a0, a1sq) * rn2;
        any = any || (dot * fabsf(dot) > 0.93f * tt);
    }
    if (!any) return;   // zeros already written by kernel 1

    // ---- in-cone (~8% of threads, spatially coherent wedge) ----
    const float4 d4 = *reinterpret_cast<const float4*>(depth + (size_t)b * HWP + pix);
    const float4 o4 = *reinterpret_cast<const float4*>(obj   + (size_t)b * HWP + pix);

    const float pd = s0.x, fr = s0.y;
    const float cf1 = fr, cf2 = 2.f * fr, cf3 = 3.f * fr;
    const float angscale = 12.0f / CUDART_PI_F;

    float dv[4] = {d4.x * o4.x, d4.y * o4.y, d4.z * o4.z, d4.w * o4.w};

    float o0[4], o1[4], o2[4];
#pragma unroll
    for (int j = 0; j < 4; j++) {
        float a0  = a0b + (float)j;
        float dot = fmaf(a0, gx, a1gy);
        float tt  = fmaf(a0, a0, a1sq) * rn2;
        float r   = dot * rsqrtf(tt);
        // Branch-free exact mask: out-of-cone -> negative -> 0; tt==0 or
        // r>1 -> NaN -> fmaxf scrubs to 0 (== jnp.nan_to_num(maximum(...))).
        float m = fmaxf(fmaf(-angscale, acosf(r), 1.0f), 0.0f);
        float d = dv[j];
        float e = fabsf(d - pd);
        float v = d * m;
        o0[j] = (e <= cf1) ? v : 0.f;
        o1[j] = (e <= cf2) ? v : 0.f;
        o2[j] = (e <= cf3) ? v : 0.f;
    }

    float* op0 = out + (size_t)b * 3 * HWP + pix;
    *reinterpret_cast<float4*>(op0)           = make_float4(o0[0], o0[1], o0[2], o0[3]);
    *reinterpret_cast<float4*>(op0 + HWP)     = make_float4(o1[0], o1[1], o1[2], o1[3]);
    *reinterpret_cast<float4*>(op0 + 2 * HWP) = make_float4(o2[0], o2[1], o2[2], o2[3]);
}

extern "C" void kernel_launch(void* const* d_in, const int* in_sizes, int n_in,
                              void* d_out, int out_size) {
    const float* depth = (const float*)d_in[0];
    const float* obj   = (const float*)d_in[1];
    const float* gaze  = (const float*)d_in[2];
    const long long* hp = (const long long*)d_in[3];
    float* out = (float*)d_out;

    fused_kernel<<<NRED + NFILL, 256>>>(depth, obj, gaze, hp, out);
    cone_kernel<<<NFILL, 256>>>(depth, obj, out);
}